// round 16
// baseline (speedup 1.0000x reference)
#include <cuda_runtime.h>
#include <cuda_bf16.h>
#include <cstdint>
#include <math.h>

#define B_   64
#define S_   512
#define E_   256
#define H_   256
#define NT_  24
#define M_   (S_ * B_)   // 32768

// ---------------------------------------------------------------------------
// Device-global scratch
// ---------------------------------------------------------------------------
__device__ float g_xW[2048ll * 32768ll];           // [n = dir*1024+gate*256+u][m = t*64+b]
__device__ float g_hall_t[(size_t)S_ * B_ * 512];  // [t][b][c]
__device__ float g_emis[(size_t)S_ * B_ * NT_];    // [t][b][tag]
__device__ int   g_maskmode;

// ---------------------------------------------------------------------------
// helpers
// ---------------------------------------------------------------------------
__device__ __forceinline__ float sigm(float x) { return 1.0f / (1.0f + expf(-x)); }

__device__ __forceinline__ void fma2(unsigned long long& d,
                                     unsigned long long a, unsigned long long b) {
    asm("fma.rn.f32x2 %0, %1, %2, %0;" : "+l"(d) : "l"(a), "l"(b));
}
__device__ __forceinline__ float2 up2(unsigned long long v) {
    return make_float2(__uint_as_float((unsigned)v), __uint_as_float((unsigned)(v >> 32)));
}
__device__ __forceinline__ uint32_t smem_u32(const void* p) {
    uint32_t a;
    asm("{ .reg .u64 t; cvta.to.shared.u64 t, %1; cvt.u32.u64 %0, t; }"
        : "=r"(a) : "l"(p));
    return a;
}
// DSMEM store: map local smem address into peer CTA's smem, store uint4
__device__ __forceinline__ void dsmem_st_v4(uint32_t local_addr, uint32_t rank, uint4 v) {
    uint32_t ra;
    asm volatile("mapa.shared::cluster.u32 %0, %1, %2;" : "=r"(ra)
                 : "r"(local_addr), "r"(rank));
    asm volatile("st.shared::cluster.v4.b32 [%0], {%1, %2, %3, %4};"
                 :: "r"(ra), "r"(v.x), "r"(v.y), "r"(v.z), "r"(v.w) : "memory");
}

__device__ __forceinline__ bool read_mask(const void* m, int i, int mode) {
    switch (mode) {
        case 0:  return ((const unsigned char*)m)[i] != 0;
        case 1:  return ((const int*)m)[i] != 0;
        case 2:  return ((const float*)m)[i] != 0.0f;
        case 3:  return ((const unsigned short*)m)[i] != 0;
        default: return true;
    }
}

// ---------------------------------------------------------------------------
// init (mask detection only; recurrence state is smem-local now)
// ---------------------------------------------------------------------------
__global__ void init_kernel(const unsigned* __restrict__ mask_words, int have_mask)
{
    if (blockIdx.x == 0 && threadIdx.x == 0) {
        int mode = 4;
        if (have_mask) {
            unsigned w = mask_words[0];
            if (w == 1u)               mode = 1;
            else if (w == 0x3F800000u) mode = 2;
            else if (w == 0x3F803F80u) mode = 3;
            else                       mode = 0;
        }
        g_maskmode = mode;
    }
}

__global__ void dummy_kernel() {}

// ---------------------------------------------------------------------------
// GEMM2 (unchanged, measured 724us): f32x2, 128x128x8 tiles.
// ---------------------------------------------------------------------------
__global__ void __launch_bounds__(256, 2) gemm2(const int* __restrict__ x,
                                                const float* __restrict__ emb,
                                                const float* __restrict__ Wf,
                                                const float* __restrict__ Wb)
{
    __shared__ float Wd[8][264];
    __shared__ float Bs[8][132];
    __shared__ int   tok[128];

    const int tid = threadIdx.x;
    const int m0  = blockIdx.x * 128;
    const int n0  = blockIdx.y * 128;
    const float* W = (n0 < 1024) ? (Wf + (size_t)n0 * E_)
                                 : (Wb + (size_t)(n0 - 1024) * E_);

    if (tid < 128) {
        int m = m0 + tid;
        int tk = x[(m & 63) * S_ + (m >> 6)];
        tok[tid] = min(max(tk, 0), 50000);
    }
    __syncthreads();

    const int tx = tid & 15;
    const int ty = tid >> 4;
    const int srow = tid >> 1;
    const int skq  = (tid & 1) * 4;
    const float* wp = W + (size_t)srow * E_ + skq;
    const float* bp = emb + (size_t)tok[srow] * E_ + skq;

    unsigned long long acc2[8][4];
#pragma unroll
    for (int i = 0; i < 8; ++i)
#pragma unroll
        for (int p = 0; p < 4; ++p) acc2[i][p] = 0ull;

    {
        float4 wv = *(const float4*)(wp);
        float4 bv = *(const float4*)(bp);
#pragma unroll
        for (int q = 0; q < 4; ++q) {
            float wq = (&wv.x)[q];
            Wd[skq + q][2 * srow]     = wq;
            Wd[skq + q][2 * srow + 1] = wq;
            Bs[skq + q][srow]         = (&bv.x)[q];
        }
    }
    __syncthreads();

    for (int kc = 0; kc < E_; kc += 8) {
        float4 wv, bv;
        const bool more = (kc + 8) < E_;
        if (more) {
            wv = *(const float4*)(wp + kc + 8);
            bv = *(const float4*)(bp + kc + 8);
        }

#pragma unroll
        for (int k = 0; k < 8; ++k) {
            ulonglong2 a01 = *(const ulonglong2*)&Wd[k][2 * (ty * 4)];
            ulonglong2 a23 = *(const ulonglong2*)&Wd[k][2 * (ty * 4) + 4];
            ulonglong2 a45 = *(const ulonglong2*)&Wd[k][2 * (64 + ty * 4)];
            ulonglong2 a67 = *(const ulonglong2*)&Wd[k][2 * (64 + ty * 4) + 4];
            ulonglong2 b01 = *(const ulonglong2*)&Bs[k][tx * 4];
            ulonglong2 b23 = *(const ulonglong2*)&Bs[k][64 + tx * 4];
            unsigned long long aa[8] = {a01.x, a01.y, a23.x, a23.y,
                                        a45.x, a45.y, a67.x, a67.y};
            unsigned long long bb[4] = {b01.x, b01.y, b23.x, b23.y};
#pragma unroll
            for (int i = 0; i < 8; ++i)
#pragma unroll
                for (int p = 0; p < 4; ++p)
                    fma2(acc2[i][p], aa[i], bb[p]);
        }
        __syncthreads();

        if (more) {
#pragma unroll
            for (int q = 0; q < 4; ++q) {
                float wq = (&wv.x)[q];
                Wd[skq + q][2 * srow]     = wq;
                Wd[skq + q][2 * srow + 1] = wq;
                Bs[skq + q][srow]         = (&bv.x)[q];
            }
            __syncthreads();
        }
    }

#pragma unroll
    for (int i = 0; i < 8; ++i) {
        int n = n0 + ((i < 4) ? (ty * 4 + i) : (64 + ty * 4 + i - 4));
        float* dst = g_xW + (size_t)n * M_ + m0;
        float2 v0 = up2(acc2[i][0]), v1 = up2(acc2[i][1]);
        float2 v2 = up2(acc2[i][2]), v3 = up2(acc2[i][3]);
        *(float4*)(dst + tx * 4)      = make_float4(v0.x, v0.y, v1.x, v1.y);
        *(float4*)(dst + 64 + tx * 4) = make_float4(v2.x, v2.y, v3.x, v3.y);
    }
}

// ---------------------------------------------------------------------------
// recur9: persistent BiLSTM, batch x unit partition, CLUSTER + DSMEM exchange.
// Grid 128 = 16 clusters of 8 CTAs. Cluster = (dir, bgroup of 8 batches);
// rank c = unit chunk [32c, 32c+32). Per step: compute (identical to recur8),
// write own 1KB h slice into all 8 cluster CTAs' smem hx[(s+1)&1] via DSMEM,
// barrier.cluster. NO global memory on the recurrence path.
// Clusters are HW gang-scheduled; the 16 clusters are fully independent.
// ---------------------------------------------------------------------------
extern __shared__ float s_dyn[];

__global__ void __launch_bounds__(256) __cluster_dims__(8, 1, 1)
recur9(const float* __restrict__ Whf,
       const float* __restrict__ Whb,
       const float* __restrict__ bihf,
       const float* __restrict__ bhhf,
       const float* __restrict__ bihb,
       const float* __restrict__ bhhb)
{
    // dynamic smem layout (floats)
    float* Wt = s_dyn;                         // [256 k][132]   135168 B
    float* hd = Wt + 256 * 132;                // [256 u][18]    18432 B (duplicated h)
    unsigned long long* part =
        (unsigned long long*)(hd + 256 * 18);  // [8 w][64 rp][10] ull, 40960 B
    float* hx = (float*)(part + 8 * 64 * 10);  // [2][256 u][8 b] 16384 B exchange

    const int tid  = threadIdx.x;
    const int dir  = blockIdx.x >> 6;
    const int g8   = (blockIdx.x >> 3) & 7;
    const int rank = blockIdx.x & 7;           // == cluster_ctarank
    const int b0   = g8 * 8;
    const int u0   = rank * 32;

    const float* Wh  = dir ? Whb : Whf;
    const float* bih = dir ? bihb : bihf;
    const float* bhh = dir ? bhhb : bhhf;

    // load Whh slice transposed: Wt[k][row], row = gate*32 + u_local
    for (int idx = tid; idx < 128 * 64; idx += 256) {
        int row = idx >> 6;
        int k4  = (idx & 63) * 4;
        int grow = (row >> 5) * 256 + u0 + (row & 31);
        float4 v = *(const float4*)&Wh[(size_t)grow * 256 + k4];
#pragma unroll
        for (int i = 0; i < 4; ++i)
            Wt[(k4 + i) * 132 + row] = (&v.x)[i];
    }
    // zero read buffer hx[0] (step 0 h_prev = 0); hx[1] fully overwritten each step
    for (int idx = tid; idx < 256 * 8; idx += 256) hx[idx] = 0.0f;

    // epilogue role: thread = (u_local = tid>>3, b = tid&7)
    const int ul = tid >> 3;
    const int bb = tid & 7;
    const int uglob = u0 + ul;
    float bi_[4], bh_[4];
#pragma unroll
    for (int g = 0; g < 4; ++g) {
        bi_[g] = bih[g * 256 + uglob];
        bh_[g] = bhh[g * 256 + uglob];
    }
    float creg = 0.0f;

    // compute role: warp w = k-chunk; lane = (rq = lane>>2, bp = lane&3)
    const int w    = tid >> 5;
    const int lane = tid & 31;
    const int rq   = lane >> 2;
    const int bp   = lane & 3;

    const uint32_t hx_addr = smem_u32(hx);

    __syncthreads();

    for (int s = 0; s < S_; ++s) {
        const int t  = dir ? (S_ - 1 - s) : s;
        const int rb = s & 1, wb = rb ^ 1;

        // xw prefetch (independent of h)
        float xw[4];
#pragma unroll
        for (int g = 0; g < 4; ++g)
            xw[g] = g_xW[(size_t)(dir * 1024 + g * 256 + uglob) * M_ + t * 64 + b0 + bb];

        // import h from own exchange buffer (peers wrote it last step), duplicate
        {
            const float* src = hx + rb * 256 * 8;
#pragma unroll
            for (int q = 0; q < 8; ++q) {
                int idx = q * 256 + tid;
                int u = idx >> 3, b2 = idx & 7;
                float v = src[idx];
                hd[u * 18 + 2 * b2]     = v;
                hd[u * 18 + 2 * b2 + 1] = v;
            }
        }
        __syncthreads();

        // compute: 16 rows x 2 b x 32 k per thread (identical to recur8)
        unsigned long long acc[8][2];
#pragma unroll
        for (int p = 0; p < 8; ++p) { acc[p][0] = 0ull; acc[p][1] = 0ull; }

#pragma unroll 4
        for (int kk = 0; kk < 32; ++kk) {
            const int k = w * 32 + kk;
            unsigned long long h0 = *(const unsigned long long*)&hd[k * 18 + 4 * bp];
            unsigned long long h1 = *(const unsigned long long*)&hd[k * 18 + 4 * bp + 2];
            const float* wrow = &Wt[k * 132 + rq * 16];
#pragma unroll
            for (int q = 0; q < 4; ++q) {
                ulonglong2 wv = *(const ulonglong2*)(wrow + q * 4);
                fma2(acc[q * 2 + 0][0], wv.x, h0);
                fma2(acc[q * 2 + 1][0], wv.y, h0);
                fma2(acc[q * 2 + 0][1], wv.x, h1);
                fma2(acc[q * 2 + 1][1], wv.y, h1);
            }
        }

#pragma unroll
        for (int p = 0; p < 8; ++p) {
            ulonglong2 v; v.x = acc[p][0]; v.y = acc[p][1];
            *(ulonglong2*)&part[((w * 64) + (rq * 8 + p)) * 10 + 2 * bp] = v;
        }
        __syncthreads();

        // epilogue: reduce 8 warp-partials, nonlinearity, state update
        {
            const float* partf = (const float*)part;
            float gv[4];
#pragma unroll
            for (int g = 0; g < 4; ++g) {
                int row = g * 32 + ul;
                int rp = row >> 1, lohi = row & 1;
                float sgm = partf[((0 * 64 + rp) * 10 + bb) * 2 + lohi];
#pragma unroll
                for (int ww = 1; ww < 8; ++ww)
                    sgm += partf[((ww * 64 + rp) * 10 + bb) * 2 + lohi];
                gv[g] = ((xw[g] + sgm) + bi_[g]) + bh_[g];
            }

            float cc = sigm(gv[1]) * creg + sigm(gv[0]) * tanhf(gv[2]);
            float h = sigm(gv[3]) * tanhf(cc);
            creg = cc;

            // local store of own slice into write buffer
            hx[(wb * 256 + uglob) * 8 + bb] = h;
            g_hall_t[((size_t)t * 64 + b0 + bb) * 512 + dir * 256 + uglob] = h;
        }
        __syncthreads();

        // broadcast own 1KB slice (64 uint4) to the 7 peer CTAs via DSMEM
        {
            const uint32_t base = hx_addr + ((wb * 256 + u0) * 8) * 4;
            for (int idx = tid; idx < 7 * 64; idx += 256) {
                int p   = idx >> 6;                 // 0..6
                int off = idx & 63;
                uint32_t pr = (uint32_t)(p + (p >= rank ? 1 : 0));
                uint4 v = *(const uint4*)((const char*)hx +
                                          ((wb * 256 + u0) * 8 + off * 4) * 4);
                dsmem_st_v4(base + off * 16, pr, v);
            }
        }

        // cluster barrier: orders DSMEM stores, releases step s
        asm volatile("barrier.cluster.arrive.aligned;" ::: "memory");
        asm volatile("barrier.cluster.wait.aligned;" ::: "memory");
    }
}

// ---------------------------------------------------------------------------
// Emission (unchanged)
// ---------------------------------------------------------------------------
__global__ void __launch_bounds__(128) emis2(const float* __restrict__ Wout,
                                             const float* __restrict__ bout)
{
    __shared__ float ws[24][512];

    const int tid = threadIdx.x;
    for (int idx = tid; idx < 3072; idx += 128)
        *(float4*)&ws[0][idx * 4] = *(const float4*)&Wout[idx * 4];
    __syncthreads();

    const int t = blockIdx.x * 2 + (tid >> 6);
    const int b = tid & 63;

    float acc[NT_];
#pragma unroll
    for (int jj = 0; jj < NT_; ++jj) acc[jj] = 0.0f;

    const float* hp = g_hall_t + ((size_t)t * 64 + b) * 512;
    for (int c = 0; c < 512; c += 4) {
        float4 hv = *(const float4*)(hp + c);
#pragma unroll
        for (int jj = 0; jj < NT_; ++jj) {
            float4 w = *(const float4*)&ws[jj][c];
            acc[jj] = fmaf(hv.x, w.x, acc[jj]);
            acc[jj] = fmaf(hv.y, w.y, acc[jj]);
            acc[jj] = fmaf(hv.z, w.z, acc[jj]);
            acc[jj] = fmaf(hv.w, w.w, acc[jj]);
        }
    }

    float* op = g_emis + ((size_t)t * 64 + b) * NT_;
#pragma unroll
    for (int jj = 0; jj < NT_; ++jj) op[jj] = acc[jj] + bout[jj];
}

// ---------------------------------------------------------------------------
// Viterbi (unchanged)
// ---------------------------------------------------------------------------
__global__ void viterbi_kernel(const void* __restrict__ mask,
                               const float* __restrict__ trans,
                               const float* __restrict__ startv,
                               const float* __restrict__ endv,
                               float* __restrict__ out)
{
    __shared__ float tr[24][25];
    __shared__ float sc[2][24];
    __shared__ unsigned char bp[511][24];
    __shared__ unsigned char msk[512];
    __shared__ int tagseq[512];

    const int b   = blockIdx.x;
    const int tid = threadIdx.x;
    const int mode = g_maskmode;

    for (int f = tid; f < 576; f += 32) tr[f / 24][f % 24] = trans[f];
    for (int f = tid; f < 512; f += 32) msk[f] = read_mask(mask, b * S_ + f, mode) ? 1 : 0;
    if (tid < 24) sc[0][tid] = startv[tid] + g_emis[(size_t)b * NT_ + tid];
    __syncwarp();

    float e_cur = 0.0f;
    if (tid < 24) e_cur = g_emis[((size_t)64 + b) * NT_ + tid];

    for (int t = 1; t < S_; ++t) {
        int pr = (t - 1) & 1, nx = t & 1;
        float e_next = 0.0f;
        if (tid < 24 && t + 1 < S_)
            e_next = g_emis[((size_t)(t + 1) * 64 + b) * NT_ + tid];
        if (tid < 24) {
            float best = (sc[pr][0] + tr[0][tid]) + e_cur;
            int bi = 0;
#pragma unroll
            for (int i = 1; i < 24; ++i) {
                float v = (sc[pr][i] + tr[i][tid]) + e_cur;
                if (v > best) { best = v; bi = i; }
            }
            if (msk[t]) {
                sc[nx][tid]    = best;
                bp[t - 1][tid] = (unsigned char)bi;
            } else {
                sc[nx][tid]    = sc[pr][tid];
                bp[t - 1][tid] = (unsigned char)tid;
            }
        }
        e_cur = e_next;
        __syncwarp();
    }

    if (tid == 0) {
        float best = sc[1][0] + endv[0];
        int bi = 0;
        for (int i = 1; i < 24; ++i) {
            float v = sc[1][i] + endv[i];
            if (v > best) { best = v; bi = i; }
        }
        int cur = bi;
        tagseq[511] = cur;
        for (int t = 511; t >= 1; --t) {
            cur = bp[t - 1][cur];
            tagseq[t - 1] = cur;
        }
    }
    __syncthreads();
    for (int t = tid; t < S_; t += 32) out[b * S_ + t] = (float)tagseq[t];
}

// ---------------------------------------------------------------------------
// launch — recur9 (cluster) at profiled slot (launch index 3).
// ---------------------------------------------------------------------------
extern "C" void kernel_launch(void* const* d_in, const int* in_sizes, int n_in,
                              void* d_out, int out_size)
{
    int ei = -1;
    for (int i = 0; i < n_in; ++i)
        if (in_sizes[i] == 50001 * 256) { ei = i; break; }
    if (ei < 0) ei = 2;

    const int*  x    = (const int*)d_in[0];
    const void* mask = (ei >= 2) ? d_in[1] : nullptr;
    int have_mask    = (ei >= 2) ? 1 : 0;

    const float* emb    = (const float*)d_in[ei];
    const float* Wihf   = (const float*)d_in[ei + 1];
    const float* Whhf   = (const float*)d_in[ei + 2];
    const float* bihf   = (const float*)d_in[ei + 3];
    const float* bhhf   = (const float*)d_in[ei + 4];
    const float* Wihb   = (const float*)d_in[ei + 5];
    const float* Whhb   = (const float*)d_in[ei + 6];
    const float* bihb   = (const float*)d_in[ei + 7];
    const float* bhhb   = (const float*)d_in[ei + 8];
    const float* Wout   = (const float*)d_in[ei + 9];
    const float* bout   = (const float*)d_in[ei + 10];
    const float* trans  = (const float*)d_in[ei + 11];
    const float* startv = (const float*)d_in[ei + 12];
    const float* endv   = (const float*)d_in[ei + 13];
    float* out = (float*)d_out;

    // Wt 135168 + hd 18432 + part 40960 + hx 16384 = 210944 B
    const int smem_recur = 210944;
    cudaFuncSetAttribute(recur9, cudaFuncAttributeMaxDynamicSharedMemorySize, smem_recur);

    init_kernel<<<1, 32>>>((const unsigned*)mask, have_mask);      // launch 0

    dim3 gg(M_ / 128, 2048 / 128);
    gemm2<<<gg, 256>>>(x, emb, Wihf, Wihb);                        // launch 1

    dummy_kernel<<<1, 32>>>();                                     // launch 2 (shim)

    recur9<<<128, 256, smem_recur>>>(Whhf, Whhb,                   // launch 3 <- profiled
                                     bihf, bhhf, bihb, bhhb);

    emis2<<<256, 128>>>(Wout, bout);                               // launch 4

    viterbi_kernel<<<64, 32>>>(mask, trans, startv, endv, out);    // launch 5
}

// round 17
// speedup vs baseline: 1.6787x; 1.6787x over previous
#include <cuda_runtime.h>
#include <cuda_bf16.h>
#include <cstdint>
#include <math.h>

#define B_   64
#define S_   512
#define E_   256
#define H_   256
#define NT_  24
#define M_   (S_ * B_)   // 32768

// ---------------------------------------------------------------------------
// Device-global scratch
// ---------------------------------------------------------------------------
__device__ float g_xW[2048ll * 32768ll];           // [n = dir*1024+gate*256+u][m = t*64+b]
__device__ float g_h[2][2][256][64];               // [dir][pingpong][unit][b]
__device__ float g_hall_t[(size_t)S_ * B_ * 512];  // [t][b][c]
__device__ float g_emis[(size_t)S_ * B_ * NT_];    // [t][b][tag]
__device__ unsigned g_barcnt[2];
__device__ int   g_maskmode;

// ---------------------------------------------------------------------------
// helpers
// ---------------------------------------------------------------------------
__device__ __forceinline__ float sigm(float x) { return 1.0f / (1.0f + expf(-x)); }

__device__ __forceinline__ unsigned ld_acq(const unsigned* p) {
    unsigned v;
    asm volatile("ld.acquire.gpu.u32 %0, [%1];" : "=r"(v) : "l"(p) : "memory");
    return v;
}
__device__ __forceinline__ void red_rel_add(unsigned* p, unsigned v) {
    asm volatile("red.release.gpu.add.u32 [%0], %1;" :: "l"(p), "r"(v) : "memory");
}
__device__ __forceinline__ void fma2(unsigned long long& d,
                                     unsigned long long a, unsigned long long b) {
    asm("fma.rn.f32x2 %0, %1, %2, %0;" : "+l"(d) : "l"(a), "l"(b));
}
__device__ __forceinline__ float2 up2(unsigned long long v) {
    return make_float2(__uint_as_float((unsigned)v), __uint_as_float((unsigned)(v >> 32)));
}

__device__ __forceinline__ bool read_mask(const void* m, int i, int mode) {
    switch (mode) {
        case 0:  return ((const unsigned char*)m)[i] != 0;
        case 1:  return ((const int*)m)[i] != 0;
        case 2:  return ((const float*)m)[i] != 0.0f;
        case 3:  return ((const unsigned short*)m)[i] != 0;
        default: return true;
    }
}

// ---------------------------------------------------------------------------
// init
// ---------------------------------------------------------------------------
__global__ void init_kernel(const unsigned* __restrict__ mask_words, int have_mask)
{
    int i = blockIdx.x * 256 + threadIdx.x;
    if (i < 2 * 2 * 256 * 64) (&g_h[0][0][0][0])[i] = 0.0f;
    if (i < 2) g_barcnt[i] = 0u;
    if (i == 0) {
        int mode = 4;
        if (have_mask) {
            unsigned w = mask_words[0];
            if (w == 1u)               mode = 1;
            else if (w == 0x3F800000u) mode = 2;
            else if (w == 0x3F803F80u) mode = 3;
            else                       mode = 0;
        }
        g_maskmode = mode;
    }
}

__global__ void dummy_kernel() {}

// ---------------------------------------------------------------------------
// GEMM2 (unchanged, measured 724us): f32x2, 128x128x8 tiles.
// ---------------------------------------------------------------------------
__global__ void __launch_bounds__(256, 2) gemm2(const int* __restrict__ x,
                                                const float* __restrict__ emb,
                                                const float* __restrict__ Wf,
                                                const float* __restrict__ Wb)
{
    __shared__ float Wd[8][264];
    __shared__ float Bs[8][132];
    __shared__ int   tok[128];

    const int tid = threadIdx.x;
    const int m0  = blockIdx.x * 128;
    const int n0  = blockIdx.y * 128;
    const float* W = (n0 < 1024) ? (Wf + (size_t)n0 * E_)
                                 : (Wb + (size_t)(n0 - 1024) * E_);

    if (tid < 128) {
        int m = m0 + tid;
        int tk = x[(m & 63) * S_ + (m >> 6)];
        tok[tid] = min(max(tk, 0), 50000);
    }
    __syncthreads();

    const int tx = tid & 15;
    const int ty = tid >> 4;
    const int srow = tid >> 1;
    const int skq  = (tid & 1) * 4;
    const float* wp = W + (size_t)srow * E_ + skq;
    const float* bp = emb + (size_t)tok[srow] * E_ + skq;

    unsigned long long acc2[8][4];
#pragma unroll
    for (int i = 0; i < 8; ++i)
#pragma unroll
        for (int p = 0; p < 4; ++p) acc2[i][p] = 0ull;

    {
        float4 wv = *(const float4*)(wp);
        float4 bv = *(const float4*)(bp);
#pragma unroll
        for (int q = 0; q < 4; ++q) {
            float wq = (&wv.x)[q];
            Wd[skq + q][2 * srow]     = wq;
            Wd[skq + q][2 * srow + 1] = wq;
            Bs[skq + q][srow]         = (&bv.x)[q];
        }
    }
    __syncthreads();

    for (int kc = 0; kc < E_; kc += 8) {
        float4 wv, bv;
        const bool more = (kc + 8) < E_;
        if (more) {
            wv = *(const float4*)(wp + kc + 8);
            bv = *(const float4*)(bp + kc + 8);
        }

#pragma unroll
        for (int k = 0; k < 8; ++k) {
            ulonglong2 a01 = *(const ulonglong2*)&Wd[k][2 * (ty * 4)];
            ulonglong2 a23 = *(const ulonglong2*)&Wd[k][2 * (ty * 4) + 4];
            ulonglong2 a45 = *(const ulonglong2*)&Wd[k][2 * (64 + ty * 4)];
            ulonglong2 a67 = *(const ulonglong2*)&Wd[k][2 * (64 + ty * 4) + 4];
            ulonglong2 b01 = *(const ulonglong2*)&Bs[k][tx * 4];
            ulonglong2 b23 = *(const ulonglong2*)&Bs[k][64 + tx * 4];
            unsigned long long aa[8] = {a01.x, a01.y, a23.x, a23.y,
                                        a45.x, a45.y, a67.x, a67.y};
            unsigned long long bb[4] = {b01.x, b01.y, b23.x, b23.y};
#pragma unroll
            for (int i = 0; i < 8; ++i)
#pragma unroll
                for (int p = 0; p < 4; ++p)
                    fma2(acc2[i][p], aa[i], bb[p]);
        }
        __syncthreads();

        if (more) {
#pragma unroll
            for (int q = 0; q < 4; ++q) {
                float wq = (&wv.x)[q];
                Wd[skq + q][2 * srow]     = wq;
                Wd[skq + q][2 * srow + 1] = wq;
                Bs[skq + q][srow]         = (&bv.x)[q];
            }
            __syncthreads();
        }
    }

#pragma unroll
    for (int i = 0; i < 8; ++i) {
        int n = n0 + ((i < 4) ? (ty * 4 + i) : (64 + ty * 4 + i - 4));
        float* dst = g_xW + (size_t)n * M_ + m0;
        float2 v0 = up2(acc2[i][0]), v1 = up2(acc2[i][1]);
        float2 v2 = up2(acc2[i][2]), v3 = up2(acc2[i][3]);
        *(float4*)(dst + tx * 4)      = make_float4(v0.x, v0.y, v1.x, v1.y);
        *(float4*)(dst + 64 + tx * 4) = make_float4(v2.x, v2.y, v3.x, v3.y);
    }
}

// ---------------------------------------------------------------------------
// recur10: recur3 skeleton, inner loop in PLAIN CUDA (no inline asm).
// 128 blocks x 256 threads, 1/SM. Warp w owns k-chunk [32w, 32w+32).
// Thread handles 16 gate rows x 1 b-pair. W: Whs[16][264] (no duplication),
// broadcast float4 loads; h: float2 from the same coalesced LDG.64s, loaded
// in two halves of 16 to bound registers. lo/hi accumulated separately in
// the identical k-ascending order -> bit-exact vs recur3.
// Partials/reduction/epilogue/barrier: byte-identical to recur3.
// ---------------------------------------------------------------------------
__global__ void __launch_bounds__(256) recur10(const float* __restrict__ Whf,
                                               const float* __restrict__ Whb,
                                               const float* __restrict__ bihf,
                                               const float* __restrict__ bhhf,
                                               const float* __restrict__ bihb,
                                               const float* __restrict__ bhhb)
{
    __shared__ float Whs[16][264];    // [r][k], r = gate*4 + j (no duplication)
    __shared__ float part[8][16][68]; // per-warp partials [w][r][b]

    const int tid = threadIdx.x;
    const int dir = blockIdx.x >> 6;
    const int us  = (blockIdx.x & 63) * 4;

    const float* Wh  = dir ? Whb : Whf;
    const float* bih = dir ? bihb : bihf;
    const float* bhh = dir ? bhhb : bhhf;

    for (int idx = tid; idx < 16 * 256; idx += 256) {
        int r  = idx >> 8;
        int kk = idx & 255;
        Whs[r][kk] = Wh[(size_t)((r >> 2) * 256 + us + (r & 3)) * 256 + kk];
    }

    // epilogue-role constants
    const int j = tid >> 6;
    const int b = tid & 63;
    const int u = us + j;
    float bi_[4], bh_[4];
#pragma unroll
    for (int g = 0; g < 4; ++g) {
        bi_[g] = bih[g * 256 + u];
        bh_[g] = bhh[g * 256 + u];
    }
    float creg = 0.0f;

    // compute-role constants
    const int w    = tid >> 5;        // warp id = k-chunk
    const int lane = tid & 31;
    const int bpx  = 2 * lane;        // b-pair base

    unsigned* bar = &g_barcnt[dir];
    __syncthreads();

    for (int s = 0; s < S_; ++s) {
        const int t  = dir ? (S_ - 1 - s) : s;
        const int rb = s & 1, wbuf = rb ^ 1;

        // xw prefetch (epilogue role)
        float xw[4];
#pragma unroll
        for (int g = 0; g < 4; ++g)
            xw[g] = g_xW[(size_t)(dir * 1024 + g * 256 + u) * M_ + t * 64 + b];

        float accL[16], accH[16];
#pragma unroll
        for (int r = 0; r < 16; ++r) { accL[r] = 0.0f; accH[r] = 0.0f; }

        // two halves of 16 k each (bounds registers; k order stays ascending)
#pragma unroll
        for (int hf = 0; hf < 2; ++hf) {
            float2 hv[16];
#pragma unroll
            for (int i = 0; i < 16; ++i)
                hv[i] = *(const float2*)&g_h[dir][rb][w * 32 + hf * 16 + i][bpx];

#pragma unroll
            for (int kq = 0; kq < 4; ++kq) {
                const int gk = w * 32 + hf * 16 + kq * 4;
                float2 h0 = hv[kq * 4 + 0];
                float2 h1 = hv[kq * 4 + 1];
                float2 h2 = hv[kq * 4 + 2];
                float2 h3 = hv[kq * 4 + 3];
#pragma unroll
                for (int r = 0; r < 16; ++r) {
                    float4 wv = *(const float4*)&Whs[r][gk];
                    accL[r] = fmaf(wv.x, h0.x, accL[r]);
                    accH[r] = fmaf(wv.x, h0.y, accH[r]);
                    accL[r] = fmaf(wv.y, h1.x, accL[r]);
                    accH[r] = fmaf(wv.y, h1.y, accH[r]);
                    accL[r] = fmaf(wv.z, h2.x, accL[r]);
                    accH[r] = fmaf(wv.z, h2.y, accH[r]);
                    accL[r] = fmaf(wv.w, h3.x, accL[r]);
                    accH[r] = fmaf(wv.w, h3.y, accH[r]);
                }
            }
        }

        // write partials (same layout as recur3: two floats at [w][r][bpx])
#pragma unroll
        for (int r = 0; r < 16; ++r) {
            float2 v; v.x = accL[r]; v.y = accH[r];
            *(float2*)&part[w][r][bpx] = v;
        }
        __syncthreads();

        // epilogue: reduce 8 partials per gate row, nonlinearity, state update
        {
            float gv[4];
#pragma unroll
            for (int g = 0; g < 4; ++g) {
                int r = g * 4 + j;
                float sgm = part[0][r][b];
#pragma unroll
                for (int ww = 1; ww < 8; ++ww) sgm += part[ww][r][b];
                gv[g] = ((xw[g] + sgm) + bi_[g]) + bh_[g];
            }

            float c = sigm(gv[1]) * creg + sigm(gv[0]) * tanhf(gv[2]);
            float h = sigm(gv[3]) * tanhf(c);
            creg = c;

            g_h[dir][wbuf][u][b] = h;
            g_hall_t[((size_t)t * 64 + b) * 512 + dir * 256 + u] = h;
        }

        __syncthreads();
        if (tid == 0) {
            red_rel_add(bar, 1u);
            unsigned target = 64u * (unsigned)(s + 1);
            while (ld_acq(bar) < target) { __nanosleep(20); }
        }
        __syncthreads();
    }
}

// ---------------------------------------------------------------------------
// Emission (unchanged)
// ---------------------------------------------------------------------------
__global__ void __launch_bounds__(128) emis2(const float* __restrict__ Wout,
                                             const float* __restrict__ bout)
{
    __shared__ float ws[24][512];

    const int tid = threadIdx.x;
    for (int idx = tid; idx < 3072; idx += 128)
        *(float4*)&ws[0][idx * 4] = *(const float4*)&Wout[idx * 4];
    __syncthreads();

    const int t = blockIdx.x * 2 + (tid >> 6);
    const int b = tid & 63;

    float acc[NT_];
#pragma unroll
    for (int jj = 0; jj < NT_; ++jj) acc[jj] = 0.0f;

    const float* hp = g_hall_t + ((size_t)t * 64 + b) * 512;
    for (int c = 0; c < 512; c += 4) {
        float4 hv = *(const float4*)(hp + c);
#pragma unroll
        for (int jj = 0; jj < NT_; ++jj) {
            float4 w = *(const float4*)&ws[jj][c];
            acc[jj] = fmaf(hv.x, w.x, acc[jj]);
            acc[jj] = fmaf(hv.y, w.y, acc[jj]);
            acc[jj] = fmaf(hv.z, w.z, acc[jj]);
            acc[jj] = fmaf(hv.w, w.w, acc[jj]);
        }
    }

    float* op = g_emis + ((size_t)t * 64 + b) * NT_;
#pragma unroll
    for (int jj = 0; jj < NT_; ++jj) op[jj] = acc[jj] + bout[jj];
}

// ---------------------------------------------------------------------------
// Viterbi (unchanged)
// ---------------------------------------------------------------------------
__global__ void viterbi_kernel(const void* __restrict__ mask,
                               const float* __restrict__ trans,
                               const float* __restrict__ startv,
                               const float* __restrict__ endv,
                               float* __restrict__ out)
{
    __shared__ float tr[24][25];
    __shared__ float sc[2][24];
    __shared__ unsigned char bp[511][24];
    __shared__ unsigned char msk[512];
    __shared__ int tagseq[512];

    const int b   = blockIdx.x;
    const int tid = threadIdx.x;
    const int mode = g_maskmode;

    for (int f = tid; f < 576; f += 32) tr[f / 24][f % 24] = trans[f];
    for (int f = tid; f < 512; f += 32) msk[f] = read_mask(mask, b * S_ + f, mode) ? 1 : 0;
    if (tid < 24) sc[0][tid] = startv[tid] + g_emis[(size_t)b * NT_ + tid];
    __syncwarp();

    float e_cur = 0.0f;
    if (tid < 24) e_cur = g_emis[((size_t)64 + b) * NT_ + tid];

    for (int t = 1; t < S_; ++t) {
        int pr = (t - 1) & 1, nx = t & 1;
        float e_next = 0.0f;
        if (tid < 24 && t + 1 < S_)
            e_next = g_emis[((size_t)(t + 1) * 64 + b) * NT_ + tid];
        if (tid < 24) {
            float best = (sc[pr][0] + tr[0][tid]) + e_cur;
            int bi = 0;
#pragma unroll
            for (int i = 1; i < 24; ++i) {
                float v = (sc[pr][i] + tr[i][tid]) + e_cur;
                if (v > best) { best = v; bi = i; }
            }
            if (msk[t]) {
                sc[nx][tid]    = best;
                bp[t - 1][tid] = (unsigned char)bi;
            } else {
                sc[nx][tid]    = sc[pr][tid];
                bp[t - 1][tid] = (unsigned char)tid;
            }
        }
        e_cur = e_next;
        __syncwarp();
    }

    if (tid == 0) {
        float best = sc[1][0] + endv[0];
        int bi = 0;
        for (int i = 1; i < 24; ++i) {
            float v = sc[1][i] + endv[i];
            if (v > best) { best = v; bi = i; }
        }
        int cur = bi;
        tagseq[511] = cur;
        for (int t = 511; t >= 1; --t) {
            cur = bp[t - 1][cur];
            tagseq[t - 1] = cur;
        }
    }
    __syncthreads();
    for (int t = tid; t < S_; t += 32) out[b * S_ + t] = (float)tagseq[t];
}

// ---------------------------------------------------------------------------
// launch — recur10 at profiled slot (launch index 3).
// ---------------------------------------------------------------------------
extern "C" void kernel_launch(void* const* d_in, const int* in_sizes, int n_in,
                              void* d_out, int out_size)
{
    int ei = -1;
    for (int i = 0; i < n_in; ++i)
        if (in_sizes[i] == 50001 * 256) { ei = i; break; }
    if (ei < 0) ei = 2;

    const int*  x    = (const int*)d_in[0];
    const void* mask = (ei >= 2) ? d_in[1] : nullptr;
    int have_mask    = (ei >= 2) ? 1 : 0;

    const float* emb    = (const float*)d_in[ei];
    const float* Wihf   = (const float*)d_in[ei + 1];
    const float* Whhf   = (const float*)d_in[ei + 2];
    const float* bihf   = (const float*)d_in[ei + 3];
    const float* bhhf   = (const float*)d_in[ei + 4];
    const float* Wihb   = (const float*)d_in[ei + 5];
    const float* Whhb   = (const float*)d_in[ei + 6];
    const float* bihb   = (const float*)d_in[ei + 7];
    const float* bhhb   = (const float*)d_in[ei + 8];
    const float* Wout   = (const float*)d_in[ei + 9];
    const float* bout   = (const float*)d_in[ei + 10];
    const float* trans  = (const float*)d_in[ei + 11];
    const float* startv = (const float*)d_in[ei + 12];
    const float* endv   = (const float*)d_in[ei + 13];
    float* out = (float*)d_out;

    init_kernel<<<512, 256>>>((const unsigned*)mask, have_mask);   // launch 0

    dim3 gg(M_ / 128, 2048 / 128);
    gemm2<<<gg, 256>>>(x, emb, Wihf, Wihb);                        // launch 1

    dummy_kernel<<<1, 32>>>();                                     // launch 2 (shim)

    recur10<<<128, 256>>>(Whhf, Whhb, bihf, bhhf, bihb, bhhb);     // launch 3 <- profiled

    emis2<<<256, 128>>>(Wout, bout);                               // launch 4

    viterbi_kernel<<<64, 32>>>(mask, trans, startv, endv, out);    // launch 5
}